// round 14
// baseline (speedup 1.0000x reference)
#include <cuda_runtime.h>
#include <math.h>

#define HID 1024
#define VOC 50257
#define SEQ 512
#define N4  12564   // floor(VOC/4); element VOC-1 handled scalar
#define NB  888     // fused-kernel grid: 148 SMs x 6 co-resident blocks
#define RB  64      // finish-kernel blocks (co-resident, 1/SM)

__device__ __align__(16) float g_alog[SEQ];
__device__ __align__(16) float g_papp[8 * HID];   // 8 i-chunk partials of attn_applied
__device__ __align__(16) float g_combe[HID];      // comb embed-half partial
__device__ __align__(16) float g_x[HID];
__device__ __align__(16) float g_gih[6 * HID];    // [gi_r gi_z gi_n gh_r gh_z gh_n]
__device__ __align__(16) float g_logits[VOC + 3];
__device__ float g_pm[RB], g_ps[RB];              // partial LSE (max, sum)
__device__ volatile int g_sync;
__device__ volatile int g_sync2;

__global__ void k_rst() { g_sync = 0; g_sync2 = 0; }

__device__ __forceinline__ float wsum(float v) {
#pragma unroll
    for (int o = 16; o; o >>= 1) v += __shfl_xor_sync(0xffffffffu, v, o);
    return v;
}
__device__ __forceinline__ float wmax(float v) {
#pragma unroll
    for (int o = 16; o; o >>= 1) v = fmaxf(v, __shfl_xor_sync(0xffffffffu, v, o));
    return v;
}
__device__ __forceinline__ float dot4(float4 a, float4 b) {
    return a.x * b.x + a.y * b.y + a.z * b.z + a.w * b.w;
}

__device__ __forceinline__ void gsync(volatile int* ctr, int target) {
    __syncthreads();
    if (threadIdx.x == 0) {
        __threadfence();
        atomicAdd((int*)ctr, 1);
        while (*ctr < target) __nanosleep(64);
        __threadfence();
    }
    __syncthreads();
}

// Fused chain: P1 (attn logits | gh | comb-embed) -> P2 (softmax+app) ->
// P3 (comb-attn half -> x) -> P4 (gi) -> P5 (gate math).
__global__ void __launch_bounds__(256, 6)
k_fused(const int* __restrict__ tok, const float* __restrict__ hid,
        const float* __restrict__ emb, const float* __restrict__ attn_W,
        const float* __restrict__ attn_b, const float* __restrict__ W_hh,
        const float* __restrict__ comb_W, const float* __restrict__ comb_b,
        const float* __restrict__ enc, const float* __restrict__ W_ih,
        const float* __restrict__ b_ih, const float* __restrict__ b_hh,
        float* __restrict__ out_h, float* __restrict__ out_attn) {
    int b = blockIdx.x, t = threadIdx.x, w = t >> 5, lane = t & 31;
    __shared__ float sp[8];
    __shared__ float red[8];
    __shared__ float bcM, bcS;
    __shared__ float w64[64];

    const float* er = emb + (long)tok[0] * HID;

    // ================= Phase 1 =================
    if (b < 256) {
        // attn logits, split-K x4 (2 rows/block, 4 warps/row)
        int gw = b * 8 + w;
        int row = gw >> 2, kc = gw & 3;
        const float* base = (kc < 2) ? (er + kc * 512) : (hid + (kc - 2) * 512);
        const float4* m = (const float4*)(attn_W + (long)row * 2 * HID + kc * 512);
        const float4* c = (const float4*)base;
        float s = 0.f;
#pragma unroll
        for (int i = 0; i < 4; i++) {
            int k = lane + 32 * i;
            s += dot4(m[k], c[k]);
        }
        s = wsum(s);
        if (lane == 0) sp[w] = s;
        __syncthreads();
        if (t < 2) {
            int r = b * 2 + t;
            g_alog[r] = sp[4 * t] + sp[4 * t + 1] + sp[4 * t + 2] + sp[4 * t + 3] + attn_b[r];
        }
    } else if (b < 640) {
        // gh = W_hh @ h0, 1 row/warp (3072 warps)
        int r = (b - 256) * 8 + w;
        const float4* hv = (const float4*)hid;
        const float4* m  = (const float4*)(W_hh + (long)r * HID);
        float s = 0.f;
#pragma unroll
        for (int i = 0; i < 8; i++) {
            int k = lane + 32 * i;
            s += dot4(__ldg(m + k), __ldg(hv + k));
        }
        s = wsum(s);
        if (lane == 0) g_gih[3 * HID + r] = s;
    } else if (b < 768) {
        // comb embed-half: 1 row/warp over first 1024 cols
        int row = (b - 640) * 8 + w;
        const float4* m  = (const float4*)(comb_W + (long)row * 2 * HID);
        const float4* ev = (const float4*)er;
        float s = 0.f;
#pragma unroll
        for (int i = 0; i < 8; i++) {
            int k = lane + 32 * i;
            s += dot4(__ldg(m + k), __ldg(ev + k));
        }
        s = wsum(s);
        if (lane == 0) g_combe[row] = s;
    }
    gsync(&g_sync, NB);

    // ================= Phase 2: softmax (redundant per block) + app =================
    if (b < 32) {
        float v0 = g_alog[t], v1 = g_alog[t + 256];
        float mx = wmax(fmaxf(v0, v1));
        if (lane == 0) red[w] = mx;
        __syncthreads();
        if (t < 32) { float x = (t < 8) ? red[t] : -1e30f; x = wmax(x); if (t == 0) bcM = x; }
        __syncthreads();
        float e0 = __expf(v0 - bcM), e1 = __expf(v1 - bcM);
        float ss = wsum(e0 + e1);
        if (lane == 0) red[w] = ss;
        __syncthreads();
        if (t < 32) { float x = (t < 8) ? red[t] : 0.f; x = wsum(x); if (t == 0) bcS = x; }
        __syncthreads();
        float inv = 1.f / bcS;
        if (b == 0) { out_attn[t] = e0 * inv; out_attn[t + 256] = e1 * inv; }
        int ic = b >> 2, jb = b & 3;            // 8 i-chunks x 4 j-blocks
        if (t < 64) w64[t] = __expf(g_alog[ic * 64 + t] - bcM) * inv;
        __syncthreads();
        int j = jb * 256 + t;
        const float* ep = enc + (long)(ic * 64) * HID + j;
        float acc = 0.f;
#pragma unroll 8
        for (int i = 0; i < 64; i++) acc += w64[i] * ep[(long)i * HID];
        g_papp[ic * HID + j] = acc;
    }
    gsync(&g_sync, 2 * NB);

    // ================= Phase 3: comb attn-half + combine -> x =================
    if (b < 256) {
        int gw = b * 8 + w;
        int row = gw >> 1, kc = gw & 1;         // 2 warps/row, 512 cols each
        const float4* a = (const float4*)(comb_W + (long)row * 2 * HID + HID + kc * 512);
        float s = 0.f;
#pragma unroll
        for (int i = 0; i < 4; i++) {
            int k = lane + 32 * i;
            float4 av = __ldg(a + k);
            int pk = kc * 128 + k;
            float bx = 0.f, by = 0.f, bz = 0.f, bw = 0.f;
#pragma unroll
            for (int c8 = 0; c8 < 8; c8++) {
                float4 q = ((const float4*)(g_papp + c8 * HID))[pk];
                bx += q.x; by += q.y; bz += q.z; bw += q.w;
            }
            s += av.x * bx + av.y * by + av.z * bz + av.w * bw;
        }
        s = wsum(s);
        if (lane == 0) sp[w] = s;
        __syncthreads();
        if (t < 4) {
            int r = b * 4 + t;
            float v = sp[2 * t] + sp[2 * t + 1] + g_combe[r] + comb_b[r];
            g_x[r] = fmaxf(v, 0.f);
        }
    }
    gsync(&g_sync, 3 * NB);

    // ================= Phase 4: gi = W_ih @ x, 1 row/warp (3072 warps) =============
    if (b < 384) {
        int r = b * 8 + w;
        const float4* xv = (const float4*)g_x;
        const float4* m  = (const float4*)(W_ih + (long)r * HID);
        float s = 0.f;
#pragma unroll
        for (int i = 0; i < 8; i++) {
            int k = lane + 32 * i;
            s += dot4(__ldg(m + k), __ldg(xv + k));
        }
        s = wsum(s);
        if (lane == 0) g_gih[r] = s;
    }
    gsync(&g_sync, 4 * NB);

    // ================= Phase 5: gate math =================
    if (b < 4) {
        int j = b * 256 + t;
        float ir  = g_gih[j]           + b_ih[j];
        float iz  = g_gih[HID + j]     + b_ih[HID + j];
        float in_ = g_gih[2 * HID + j] + b_ih[2 * HID + j];
        float hr  = g_gih[3 * HID + j] + b_hh[j];
        float hz  = g_gih[4 * HID + j] + b_hh[HID + j];
        float hn  = g_gih[5 * HID + j] + b_hh[2 * HID + j];
        float r = 1.f / (1.f + __expf(-(ir + hr)));
        float z = 1.f / (1.f + __expf(-(iz + hz)));
        float n = tanhf(in_ + r * hn);
        out_h[j] = (1.f - z) * n + z * hid[j];
    }
}

// K5: logits = h_new @ out_W.T + out_b  (206 MB stream; 8 rows/warp) -- unchanged.
__global__ void k_out(const float* __restrict__ out_h, const float* __restrict__ out_W,
                      const float* __restrict__ out_b) {
    __shared__ __align__(16) float h[HID];
    int t = threadIdx.x;
    for (int i = t; i < HID; i += 256) h[i] = out_h[i];
    __syncthreads();
    int w = t >> 5, lane = t & 31;
    int r0 = blockIdx.x * 64 + w * 8;
    if (r0 >= VOC) return;
    const float4* c = (const float4*)h;
    const float4* mp[8];
#pragma unroll
    for (int j = 0; j < 8; j++) {
        int r = min(r0 + j, VOC - 1);
        mp[j] = (const float4*)(out_W + (long)r * HID);
    }
    float acc[8] = {0.f, 0.f, 0.f, 0.f, 0.f, 0.f, 0.f, 0.f};
#pragma unroll
    for (int i = 0; i < 8; i++) {
        int k = lane + 32 * i;
        float4 b = c[k];
#pragma unroll
        for (int j = 0; j < 8; j++) acc[j] += dot4(__ldcs(mp[j] + k), b);
    }
#pragma unroll
    for (int j = 0; j < 8; j++) acc[j] = wsum(acc[j]);
    if (lane == 0) {
#pragma unroll
        for (int j = 0; j < 8; j++)
            if (r0 + j < VOC) g_logits[r0 + j] = acc[j] + out_b[r0 + j];
    }
}

// K6: fused LSE + logp: RB co-resident blocks x 1024; spin-sync between phases.
__global__ void __launch_bounds__(1024) k_finish(float* __restrict__ out) {
    int t = threadIdx.x, b = blockIdx.x;
    const float4* L4 = (const float4*)g_logits;
    // ---- phase A: partial online LSE over strided slice ----
    float m = -1e30f, s = 0.f;
    for (int i = b * 1024 + t; i < N4; i += RB * 1024) {
        float4 v = L4[i];
        float lm = fmaxf(fmaxf(v.x, v.y), fmaxf(v.z, v.w));
        if (lm > m) { s = s * __expf(m - lm); m = lm; }
        s += __expf(v.x - m) + __expf(v.y - m) + __expf(v.z - m) + __expf(v.w - m);
    }
    if (b == 0 && t == 0) {
        float v = g_logits[VOC - 1];
        if (v > m) { s = s * __expf(m - v); m = v; }
        s += __expf(v - m);
    }
#pragma unroll
    for (int o = 16; o; o >>= 1) {
        float om = __shfl_xor_sync(0xffffffffu, m, o);
        float os = __shfl_xor_sync(0xffffffffu, s, o);
        if (om > m) { s = s * __expf(m - om) + os; m = om; }
        else          s += os * __expf(om - m);
    }
    __shared__ float shm[32], shs[32];
    if ((t & 31) == 0) { shm[t >> 5] = m; shs[t >> 5] = s; }
    __syncthreads();
    if (t == 0) {
        float M = shm[0], S = shs[0];
        for (int i = 1; i < 32; i++) {
            float om = shm[i], os = shs[i];
            if (om > M) { S = S * __expf(M - om) + os; M = om; }
            else          S += os * __expf(om - M);
        }
        g_pm[b] = M; g_ps[b] = S;
    }
    gsync(&g_sync2, RB);
    // ---- phase B: combine partials (thread 0) + write slice ----
    __shared__ float s_off;
    if (t == 0) {
        float M = g_pm[0], S = g_ps[0];
        for (int i = 1; i < RB; i++) {
            float om = g_pm[i], os = g_ps[i];
            if (om > M) { S = S * __expf(M - om) + os; M = om; }
            else          S += os * __expf(om - M);
        }
        s_off = M + logf(S);
    }
    __syncthreads();
    float off = s_off;
    float4* O4 = (float4*)out;
    for (int i = b * 1024 + t; i < N4; i += RB * 1024) {
        float4 v = L4[i];
        v.x -= off; v.y -= off; v.z -= off; v.w -= off;
        O4[i] = v;
    }
    if (b == 0 && t == 0) out[VOC - 1] = g_logits[VOC - 1] - off;
}

extern "C" void kernel_launch(void* const* d_in, const int* in_sizes, int n_in,
                              void* d_out, int out_size) {
    const int*   tok    = (const int*)d_in[0];
    const float* hidden = (const float*)d_in[1];
    const float* enc    = (const float*)d_in[2];
    const float* emb    = (const float*)d_in[3];
    const float* attn_W = (const float*)d_in[4];
    const float* attn_b = (const float*)d_in[5];
    const float* comb_W = (const float*)d_in[6];
    const float* comb_b = (const float*)d_in[7];
    const float* W_ih   = (const float*)d_in[8];
    const float* W_hh   = (const float*)d_in[9];
    const float* b_ih   = (const float*)d_in[10];
    const float* b_hh   = (const float*)d_in[11];
    const float* out_W  = (const float*)d_in[12];
    const float* out_b  = (const float*)d_in[13];

    float* out      = (float*)d_out;         // logp  [50257]
    float* out_h    = out + VOC;             // h_new [1024]
    float* out_attn = out + VOC + HID;       // attn_weights [512]

    k_rst<<<1, 1>>>();
    k_fused<<<NB, 256>>>(tok, hidden, emb, attn_W, attn_b, W_hh,
                         comb_W, comb_b, enc, W_ih, b_ih, b_hh,
                         out_h, out_attn);
    k_out<<<(VOC + 63) / 64, 256>>>(out_h, out_W, out_b);
    k_finish<<<RB, 1024>>>(out);
}

// round 15
// speedup vs baseline: 1.1010x; 1.1010x over previous
#include <cuda_runtime.h>
#include <math.h>

#define HID 1024
#define VOC 50257
#define SEQ 512
#define N4    12564   // floor(VOC/4); element VOC-1 handled scalar
#define NB    592     // fused-kernel grid: 148 SMs x 4 co-resident blocks
#define NBOUT 786     // k_out grid = ceil(VOC/64)

__device__ __align__(16) float g_alog[SEQ];
__device__ __align__(16) float g_papp[8 * HID];   // 8 i-chunk partials of attn_applied
__device__ __align__(16) float g_combe[HID];      // comb embed-half partial
__device__ __align__(16) float g_x[HID];
__device__ __align__(16) float g_gih[6 * HID];    // [gi_r gi_z gi_n gh_r gh_z gh_n]
__device__ __align__(16) float g_logits[VOC + 3];
__device__ float g_pm[NBOUT], g_ps[NBOUT];        // per-k_out-block LSE partials
__device__ volatile int g_sync;

__global__ void k_rst() { g_sync = 0; }

__device__ __forceinline__ float wsum(float v) {
#pragma unroll
    for (int o = 16; o; o >>= 1) v += __shfl_xor_sync(0xffffffffu, v, o);
    return v;
}
__device__ __forceinline__ float wmax(float v) {
#pragma unroll
    for (int o = 16; o; o >>= 1) v = fmaxf(v, __shfl_xor_sync(0xffffffffu, v, o));
    return v;
}
__device__ __forceinline__ float dot4(float4 a, float4 b) {
    return a.x * b.x + a.y * b.y + a.z * b.z + a.w * b.w;
}

__device__ __forceinline__ void gsync(int target) {
    __syncthreads();
    if (threadIdx.x == 0) {
        __threadfence();
        atomicAdd((int*)&g_sync, 1);
        while (g_sync < target) __nanosleep(64);
        __threadfence();
    }
    __syncthreads();
}

// Fused chain (identical to R13 66.3us config): P1 (attn | gh | comb-embed) ->
// P2 (softmax+app) -> P3 (comb-attn -> x) -> P4 (gi) -> P5 (gate).
__global__ void __launch_bounds__(256, 4)
k_fused(const int* __restrict__ tok, const float* __restrict__ hid,
        const float* __restrict__ emb, const float* __restrict__ attn_W,
        const float* __restrict__ attn_b, const float* __restrict__ W_hh,
        const float* __restrict__ comb_W, const float* __restrict__ comb_b,
        const float* __restrict__ enc, const float* __restrict__ W_ih,
        const float* __restrict__ b_ih, const float* __restrict__ b_hh,
        float* __restrict__ out_h, float* __restrict__ out_attn) {
    int b = blockIdx.x, t = threadIdx.x, w = t >> 5, lane = t & 31;
    __shared__ float sp[8];
    __shared__ float red[8];
    __shared__ float bcM, bcS;
    __shared__ float w64[64];

    const float* er = emb + (long)tok[0] * HID;

    // ================= Phase 1 =================
    if (b < 256) {
        // attn logits, split-K x4 (2 rows/block, 4 warps/row)
        int gw = b * 8 + w;
        int row = gw >> 2, kc = gw & 3;
        const float* base = (kc < 2) ? (er + kc * 512) : (hid + (kc - 2) * 512);
        const float4* m = (const float4*)(attn_W + (long)row * 2 * HID + kc * 512);
        const float4* c = (const float4*)base;
        float s = 0.f;
#pragma unroll
        for (int i = 0; i < 4; i++) {
            int k = lane + 32 * i;
            s += dot4(m[k], c[k]);
        }
        s = wsum(s);
        if (lane == 0) sp[w] = s;
        __syncthreads();
        if (t < 2) {
            int r = b * 2 + t;
            g_alog[r] = sp[4 * t] + sp[4 * t + 1] + sp[4 * t + 2] + sp[4 * t + 3] + attn_b[r];
        }
    } else if (b < 448) {
        // gh = W_hh @ h0, 2 rows/warp
        int r0 = (b - 256) * 16 + w * 2;
        const float4* hv = (const float4*)hid;
        const float4* m0 = (const float4*)(W_hh + (long)r0 * HID);
        const float4* m1 = m0 + 256;
        float s0 = 0.f, s1 = 0.f;
#pragma unroll
        for (int i = 0; i < 8; i++) {
            int k = lane + 32 * i;
            float4 bv = __ldg(hv + k);
            s0 += dot4(__ldg(m0 + k), bv);
            s1 += dot4(__ldg(m1 + k), bv);
        }
        s0 = wsum(s0); s1 = wsum(s1);
        if (lane == 0) { g_gih[3 * HID + r0] = s0; g_gih[3 * HID + r0 + 1] = s1; }
    } else if (b < 576) {
        // comb embed-half: 1 row/warp over first 1024 cols
        int row = (b - 448) * 8 + w;
        const float4* m  = (const float4*)(comb_W + (long)row * 2 * HID);
        const float4* ev = (const float4*)er;
        float s = 0.f;
#pragma unroll
        for (int i = 0; i < 8; i++) {
            int k = lane + 32 * i;
            s += dot4(__ldg(m + k), __ldg(ev + k));
        }
        s = wsum(s);
        if (lane == 0) g_combe[row] = s;
    }
    gsync(NB);

    // ================= Phase 2: softmax (redundant per block) + app =================
    if (b < 32) {
        float v0 = g_alog[t], v1 = g_alog[t + 256];
        float mx = wmax(fmaxf(v0, v1));
        if (lane == 0) red[w] = mx;
        __syncthreads();
        if (t < 32) { float x = (t < 8) ? red[t] : -1e30f; x = wmax(x); if (t == 0) bcM = x; }
        __syncthreads();
        float e0 = __expf(v0 - bcM), e1 = __expf(v1 - bcM);
        float ss = wsum(e0 + e1);
        if (lane == 0) red[w] = ss;
        __syncthreads();
        if (t < 32) { float x = (t < 8) ? red[t] : 0.f; x = wsum(x); if (t == 0) bcS = x; }
        __syncthreads();
        float inv = 1.f / bcS;
        if (b == 0) { out_attn[t] = e0 * inv; out_attn[t + 256] = e1 * inv; }
        int ic = b >> 2, jb = b & 3;            // 8 i-chunks x 4 j-blocks
        if (t < 64) w64[t] = __expf(g_alog[ic * 64 + t] - bcM) * inv;
        __syncthreads();
        int j = jb * 256 + t;
        const float* ep = enc + (long)(ic * 64) * HID + j;
        float acc = 0.f;
#pragma unroll 8
        for (int i = 0; i < 64; i++) acc += w64[i] * ep[(long)i * HID];
        g_papp[ic * HID + j] = acc;
    }
    gsync(2 * NB);

    // ================= Phase 3: comb attn-half + combine -> x =================
    if (b < 256) {
        int gw = b * 8 + w;
        int row = gw >> 1, kc = gw & 1;         // 2 warps/row, 512 cols each
        const float4* a = (const float4*)(comb_W + (long)row * 2 * HID + HID + kc * 512);
        float s = 0.f;
#pragma unroll
        for (int i = 0; i < 4; i++) {
            int k = lane + 32 * i;
            float4 av = __ldg(a + k);
            int pk = kc * 128 + k;
            float bx = 0.f, by = 0.f, bz = 0.f, bw = 0.f;
#pragma unroll
            for (int c8 = 0; c8 < 8; c8++) {
                float4 q = ((const float4*)(g_papp + c8 * HID))[pk];
                bx += q.x; by += q.y; bz += q.z; bw += q.w;
            }
            s += av.x * bx + av.y * by + av.z * bz + av.w * bw;
        }
        s = wsum(s);
        if (lane == 0) sp[w] = s;
        __syncthreads();
        if (t < 4) {
            int r = b * 4 + t;
            float v = sp[2 * t] + sp[2 * t + 1] + g_combe[r] + comb_b[r];
            g_x[r] = fmaxf(v, 0.f);
        }
    }
    gsync(3 * NB);

    // ================= Phase 4: gi = W_ih @ x, 2 rows/warp =================
    if (b < 192) {
        int r0 = b * 16 + w * 2;
        const float4* xv = (const float4*)g_x;
        const float4* m0 = (const float4*)(W_ih + (long)r0 * HID);
        const float4* m1 = m0 + 256;
        float s0 = 0.f, s1 = 0.f;
#pragma unroll
        for (int i = 0; i < 8; i++) {
            int k = lane + 32 * i;
            float4 bv = __ldg(xv + k);
            s0 += dot4(__ldg(m0 + k), bv);
            s1 += dot4(__ldg(m1 + k), bv);
        }
        s0 = wsum(s0); s1 = wsum(s1);
        if (lane == 0) { g_gih[r0] = s0; g_gih[r0 + 1] = s1; }
    }
    gsync(4 * NB);

    // ================= Phase 5: gate math =================
    if (b < 4) {
        int j = b * 256 + t;
        float ir  = g_gih[j]           + b_ih[j];
        float iz  = g_gih[HID + j]     + b_ih[HID + j];
        float in_ = g_gih[2 * HID + j] + b_ih[2 * HID + j];
        float hr  = g_gih[3 * HID + j] + b_hh[j];
        float hz  = g_gih[4 * HID + j] + b_hh[HID + j];
        float hn  = g_gih[5 * HID + j] + b_hh[2 * HID + j];
        float r = 1.f / (1.f + __expf(-(ir + hr)));
        float z = 1.f / (1.f + __expf(-(iz + hz)));
        float n = tanhf(in_ + r * hn);
        out_h[j] = (1.f - z) * n + z * hid[j];
    }
}

// K5: logits = h_new @ out_W.T + out_b (8 rows/warp) + per-block LSE partial
//     (no separate 400KB LSE read pass needed).
__global__ void k_out(const float* __restrict__ out_h, const float* __restrict__ out_W,
                      const float* __restrict__ out_b) {
    __shared__ __align__(16) float h[HID];
    __shared__ float sm[8], ss[8];
    int t = threadIdx.x;
    for (int i = t; i < HID; i += 256) h[i] = out_h[i];
    __syncthreads();
    int w = t >> 5, lane = t & 31;
    int r0 = blockIdx.x * 64 + w * 8;
    const float4* c = (const float4*)h;
    const float4* mp[8];
#pragma unroll
    for (int j = 0; j < 8; j++) {
        int r = min(r0 + j, VOC - 1);
        mp[j] = (const float4*)(out_W + (long)r * HID);
    }
    float acc[8] = {0.f, 0.f, 0.f, 0.f, 0.f, 0.f, 0.f, 0.f};
#pragma unroll
    for (int i = 0; i < 8; i++) {
        int k = lane + 32 * i;
        float4 b = c[k];
#pragma unroll
        for (int j = 0; j < 8; j++) acc[j] += dot4(__ldcs(mp[j] + k), b);
    }
#pragma unroll
    for (int j = 0; j < 8; j++) acc[j] = wsum(acc[j]);
    float lm = -1e30f, ls = 0.f;
    if (lane == 0) {
#pragma unroll
        for (int j = 0; j < 8; j++) {
            if (r0 + j < VOC) {
                float v = acc[j] + out_b[r0 + j];
                g_logits[r0 + j] = v;
                if (v > lm) { ls = ls * __expf(lm - v) + 1.f; lm = v; }
                else          ls += __expf(v - lm);
            }
        }
        sm[w] = lm; ss[w] = ls;
    }
    __syncthreads();
    if (t == 0) {
        float M = sm[0], S = ss[0];
#pragma unroll
        for (int i = 1; i < 8; i++) {
            float om = sm[i], os = ss[i];
            if (om > M) { S = S * __expf(M - om) + os; M = om; }
            else          S += os * __expf(om - M);
        }
        g_pm[blockIdx.x] = M; g_ps[blockIdx.x] = S;
    }
}

// K6: each block combines the 786 partials in parallel (1/thread) then writes its slice.
__global__ void __launch_bounds__(1024) k_logp(float* __restrict__ out) {
    __shared__ float shm[32], shs[32];
    __shared__ float s_off;
    int t = threadIdx.x;
    float m = (t < NBOUT) ? g_pm[t] : -1e30f;
    float s = (t < NBOUT) ? g_ps[t] : 0.f;
#pragma unroll
    for (int o = 16; o; o >>= 1) {
        float om = __shfl_xor_sync(0xffffffffu, m, o);
        float os = __shfl_xor_sync(0xffffffffu, s, o);
        if (om > m) { s = s * __expf(m - om) + os; m = om; }
        else          s += os * __expf(om - m);
    }
    if ((t & 31) == 0) { shm[t >> 5] = m; shs[t >> 5] = s; }
    __syncthreads();
    if (t == 0) {
        float M = shm[0], S = shs[0];
#pragma unroll
        for (int i = 1; i < 32; i++) {
            float om = shm[i], os = shs[i];
            if (om > M) { S = S * __expf(M - om) + os; M = om; }
            else          S += os * __expf(om - M);
        }
        s_off = M + logf(S);
    }
    __syncthreads();
    float off = s_off;
    int i = blockIdx.x * 1024 + t;
    if (i < N4) {
        float4 v = ((const float4*)g_logits)[i];
        v.x -= off; v.y -= off; v.z -= off; v.w -= off;
        ((float4*)out)[i] = v;
    }
    if (i == 0) out[VOC - 1] = g_logits[VOC - 1] - off;
}

extern "C" void kernel_launch(void* const* d_in, const int* in_sizes, int n_in,
                              void* d_out, int out_size) {
    const int*   tok    = (const int*)d_in[0];
    const float* hidden = (const float*)d_in[1];
    const float* enc    = (const float*)d_in[2];
    const float* emb    = (const float*)d_in[3];
    const float* attn_W = (const float*)d_in[4];
    const float* attn_b = (const float*)d_in[5];
    const float* comb_W = (const float*)d_in[6];
    const float* comb_b = (const float*)d_in[7];
    const float* W_ih   = (const float*)d_in[8];
    const float* W_hh   = (const float*)d_in[9];
    const float* b_ih   = (const float*)d_in[10];
    const float* b_hh   = (const float*)d_in[11];
    const float* out_W  = (const float*)d_in[12];
    const float* out_b  = (const float*)d_in[13];

    float* out      = (float*)d_out;         // logp  [50257]
    float* out_h    = out + VOC;             // h_new [1024]
    float* out_attn = out + VOC + HID;       // attn_weights [512]

    k_rst<<<1, 1>>>();
    k_fused<<<NB, 256>>>(tok, hidden, emb, attn_W, attn_b, W_hh,
                         comb_W, comb_b, enc, W_ih, b_ih, b_hh,
                         out_h, out_attn);
    k_out<<<NBOUT, 256>>>(out_h, out_W, out_b);
    k_logp<<<(N4 + 1023) / 1024, 1024>>>(out);
}